// round 8
// baseline (speedup 1.0000x reference)
#include <cuda_runtime.h>
#include <cuda_fp16.h>
#include <math.h>

#define NSIDE 512
#define NPIX  (512*512)
#define NF    257

typedef unsigned long long u64;

// ---- scratch ----
__device__ __align__(16) __half2 g_tmpR[NF * NPIX / 2];  // re plane, [f][q][y], fp16 x-pairs
__device__ __align__(16) __half2 g_tmpI[NF * NPIX / 2];  // im plane
__device__ __align__(16) __half  g_m[NF * NPIX];         // modulus*512, [f][q][y][parity]
__device__ float g_gram[32 * 16 * 24];
__device__ float g_a2;
__device__ ulonglong2 g_twp[512];                        // {(c,c),(s,s)} fp32-pairs

// ---- packed f32x2 helpers (SoA: no swaps ever) ----
__device__ __forceinline__ u64 pk2(float x, float y){ u64 r; asm("mov.b64 %0,{%1,%2};":"=l"(r):"f"(x),"f"(y)); return r; }
__device__ __forceinline__ float2 up2(u64 a){ float2 v; asm("mov.b64 {%0,%1},%2;":"=f"(v.x),"=f"(v.y):"l"(a)); return v; }
__device__ __forceinline__ u64 padd(u64 a,u64 b){ u64 r; asm("add.rn.f32x2 %0,%1,%2;":"=l"(r):"l"(a),"l"(b)); return r; }
__device__ __forceinline__ u64 pmul(u64 a,u64 b){ u64 r; asm("mul.rn.f32x2 %0,%1,%2;":"=l"(r):"l"(a),"l"(b)); return r; }
__device__ __forceinline__ u64 pfma(u64 a,u64 b,u64 c){ u64 r; asm("fma.rn.f32x2 %0,%1,%2,%3;":"=l"(r):"l"(a),"l"(b),"l"(c)); return r; }

#define DECL_S_CONSTS \
  const u64 NEG1 = pk2(-1.f, -1.f); \
  const u64 CCp = pk2(0.70710678118654752440f, 0.70710678118654752440f); \
  const u64 NCp = pk2(-0.70710678118654752440f, -0.70710678118654752440f);

// 8-pt DFT, +i sign, natural order, SoA packed (2 pixels per op)
__device__ __forceinline__ void fft8s(u64 R[8], u64 I[8], u64 NEG1, u64 CCp, u64 NCp) {
  u64 es0R=padd(R[0],R[4]), es0I=padd(I[0],I[4]);
  u64 ed0R=pfma(R[4],NEG1,R[0]), ed0I=pfma(I[4],NEG1,I[0]);
  u64 es1R=padd(R[2],R[6]), es1I=padd(I[2],I[6]);
  u64 ed1R=pfma(R[6],NEG1,R[2]), ed1I=pfma(I[6],NEG1,I[2]);
  u64 E0R=padd(es0R,es1R), E0I=padd(es0I,es1I);
  u64 E2R=pfma(es1R,NEG1,es0R), E2I=pfma(es1I,NEG1,es0I);
  u64 E1R=pfma(ed1I,NEG1,ed0R), E1I=padd(ed0I,ed1R);      // ed0 + i*ed1
  u64 E3R=padd(ed0R,ed1I),      E3I=pfma(ed1R,NEG1,ed0I); // ed0 - i*ed1
  u64 os0R=padd(R[1],R[5]), os0I=padd(I[1],I[5]);
  u64 od0R=pfma(R[5],NEG1,R[1]), od0I=pfma(I[5],NEG1,I[1]);
  u64 os1R=padd(R[3],R[7]), os1I=padd(I[3],I[7]);
  u64 od1R=pfma(R[7],NEG1,R[3]), od1I=pfma(I[7],NEG1,I[3]);
  u64 O0R=padd(os0R,os1R), O0I=padd(os0I,os1I);
  u64 O2R=pfma(os1R,NEG1,os0R), O2I=pfma(os1I,NEG1,os0I);
  u64 O1R=pfma(od1I,NEG1,od0R), O1I=padd(od0I,od1R);
  u64 O3R=padd(od0R,od1I),      O3I=pfma(od1R,NEG1,od0I);
  u64 O1tR=pmul(pfma(O1I,NEG1,O1R), CCp);   // C(x-y)
  u64 O1tI=pmul(padd(O1R,O1I), CCp);        // C(x+y)
  u64 O3tR=pmul(padd(O3R,O3I), NCp);        // -C(x+y)
  u64 O3tI=pmul(pfma(O3I,NEG1,O3R), CCp);   // C(x-y)
  R[0]=padd(E0R,O0R);        I[0]=padd(E0I,O0I);
  R[4]=pfma(O0R,NEG1,E0R);   I[4]=pfma(O0I,NEG1,E0I);
  R[1]=padd(E1R,O1tR);       I[1]=padd(E1I,O1tI);
  R[5]=pfma(O1tR,NEG1,E1R);  I[5]=pfma(O1tI,NEG1,E1I);
  R[2]=pfma(O2I,NEG1,E2R);   I[2]=padd(E2I,O2R);          // E2 + i*O2
  R[6]=padd(E2R,O2I);        I[6]=pfma(O2R,NEG1,E2I);     // E2 - i*O2
  R[3]=padd(E3R,O3tR);       I[3]=padd(E3I,O3tI);
  R[7]=pfma(O3tR,NEG1,E3R);  I[7]=pfma(O3tI,NEG1,E3I);
}

__device__ __forceinline__ void ctws(u64& Rr, u64& Ii, ulonglong2 w) {  // *(c + i s)
  u64 nss = w.y ^ 0x8000000080000000ULL;
  u64 r = pfma(Ii, nss, pmul(Rr, w.x));
  u64 i = pfma(Rr, w.y, pmul(Ii, w.x));
  Rr = r; Ii = i;
}

// 8x8 transpose among 8 lanes differing in low-3 lane bits (u64 shuffles)
__device__ __forceinline__ void transpose8u(u64 v[8], int f3) {
#pragma unroll
  for (int mb = 0; mb < 3; mb++) {
    const int m = 1 << mb;
#pragma unroll
    for (int i = 0; i < 8; i++) {
      if ((i & m) == 0) {
        const int ip = i | m;
        const bool hi = (f3 & m) != 0;
        u64 send = hi ? v[i] : v[ip];
        u64 got = __shfl_xor_sync(0xffffffffu, send, m);
        if (hi) v[i] = got; else v[ip] = got;
      }
    }
  }
}

__global__ void init_kernel() {
  int t = threadIdx.x;
  for (int m = t; m < 512; m += 256) {
    float s, c;
    sincospif((float)m * (1.0f / 256.0f), &s, &c);
    g_twp[m] = make_ulonglong2(pk2(c, c), pk2(s, s));
  }
  for (int i = t; i < 32 * 384; i += 256) g_gram[i] = 0.f;
  if (t == 0) g_a2 = 0.f;
}

// ---- stage 1: product + 512-pt IFFT along x (SoA fp32x2, y-pairs); re-pair to x-pairs; fp16 SoA store ----
__global__ void __launch_bounds__(256) rows_kernel(const float2* __restrict__ xh2,
                                                   const float* __restrict__ pre,
                                                   const float* __restrict__ pim) {
  __shared__ u64 SR[2304], SI[2304];   // stage: 4*576; final: [p][512] (2048)
  DECL_S_CONSTS
  const int tid = threadIdx.x;
  const int p = tid >> 6, t = tid & 63;
  const int f = blockIdx.y;
  const int y0 = blockIdx.x << 3;
  const int yE = y0 + 2 * p;
  const size_t rEo = (size_t)yE * NSIDE, rOo = rEo + NSIDE;
  const size_t fb = (size_t)f * NPIX;

  u64 R[8], I[8];
#pragma unroll
  for (int q = 0; q < 8; q++) {
    int x = t + (q << 6);
    float2 xcE = xh2[rEo + x], xcO = xh2[rOo + x];
    float prE = __ldcs(pre + fb + rEo + x), piE = __ldcs(pim + fb + rEo + x);
    float prO = __ldcs(pre + fb + rOo + x), piO = __ldcs(pim + fb + rOo + x);
    R[q] = pk2(xcE.x * prE - xcE.y * piE, xcO.x * prO - xcO.y * piO);
    I[q] = pk2(xcE.x * piE + xcE.y * prE, xcO.x * piO + xcO.y * prO);
  }
  fft8s(R, I, NEG1, CCp, NCp);
  u64 *SRr = SR + p * 576, *SIr = SI + p * 576;
  SRr[t] = R[0]; SIr[t] = I[0];
#pragma unroll
  for (int r = 1; r < 8; r++) {
    ctws(R[r], I[r], g_twp[t * r]);
    SRr[r * 72 + t] = R[r]; SIr[r * 72 + t] = I[r];
  }
  __syncthreads();

  const int r = t >> 3, T = t & 7;
#pragma unroll
  for (int q = 0; q < 8; q++) {
    R[q] = SRr[r * 72 + T + (q << 3)];
    I[q] = SIr[r * 72 + T + (q << 3)];
  }
  fft8s(R, I, NEG1, CCp, NCp);
#pragma unroll
  for (int rp = 1; rp < 8; rp++) ctws(R[rp], I[rp], g_twp[8 * T * rp]);
  transpose8u(R, T);
  transpose8u(I, T);
  fft8s(R, I, NEG1, CCp, NCp);
  __syncthreads();

  // final stage: [p][x] planes; then read x-pairs per y
#pragma unroll
  for (int k3 = 0; k3 < 8; k3++) {
    int x = (k3 << 6) + t;
    SR[p * 512 + x] = R[k3];
    SI[p * 512 + x] = I[k3];
  }
  __syncthreads();

  {
    const int q = tid;   // x-pair index 0..255
    unsigned hR[8], hI[8];
#pragma unroll
    for (int pp = 0; pp < 4; pp++) {
      ulonglong2 ra = *(const ulonglong2*)&SR[pp * 512 + 2 * q];
      ulonglong2 ia = *(const ulonglong2*)&SI[pp * 512 + 2 * q];
      float2 a = up2(ra.x), b = up2(ra.y);   // (x=2q: yE,yO), (x=2q+1: yE,yO)
      float2 c = up2(ia.x), d = up2(ia.y);
      __half2 h0 = __floats2half2_rn(a.x, b.x), h1 = __floats2half2_rn(a.y, b.y);
      __half2 h2v = __floats2half2_rn(c.x, d.x), h3 = __floats2half2_rn(c.y, d.y);
      hR[2*pp]   = *reinterpret_cast<unsigned*>(&h0);
      hR[2*pp+1] = *reinterpret_cast<unsigned*>(&h1);
      hI[2*pp]   = *reinterpret_cast<unsigned*>(&h2v);
      hI[2*pp+1] = *reinterpret_cast<unsigned*>(&h3);
    }
    size_t base = ((size_t)f * 256 + q) * 512 + y0;
    uint4* dR = reinterpret_cast<uint4*>(g_tmpR + base);
    dR[0] = make_uint4(hR[0], hR[1], hR[2], hR[3]);
    dR[1] = make_uint4(hR[4], hR[5], hR[6], hR[7]);
    uint4* dI = reinterpret_cast<uint4*>(g_tmpI + base);
    dI[0] = make_uint4(hI[0], hI[1], hI[2], hI[3]);
    dI[1] = make_uint4(hI[4], hI[5], hI[6], hI[7]);
  }
}

// ---- stage 2: 512-pt IFFT along y (SoA fp32x2, x-pairs) + packed modulus ----
// grid.x = 64: q = blockIdx.x*4 + cc covers exactly 0..255 x-pairs per filter.
__global__ void __launch_bounds__(256) cols_kernel() {
  __shared__ u64 SR[2304], SI[2304];
  __shared__ float red[8];
  DECL_S_CONSTS
  const int tid = threadIdx.x;
  const int cc = tid >> 6, t = tid & 63;
  const int f = blockIdx.y;
  const int q = (blockIdx.x << 2) + cc;
  const size_t base = ((size_t)f * 256 + q) * 512;

  u64 R[8], I[8];
#pragma unroll
  for (int k = 0; k < 8; k++) {
    float2 a = __half22float2(g_tmpR[base + t + (k << 6)]);
    float2 b = __half22float2(g_tmpI[base + t + (k << 6)]);
    R[k] = pk2(a.x, a.y);
    I[k] = pk2(b.x, b.y);
  }
  fft8s(R, I, NEG1, CCp, NCp);
  u64 *SRr = SR + cc * 576, *SIr = SI + cc * 576;
  SRr[t] = R[0]; SIr[t] = I[0];
#pragma unroll
  for (int r = 1; r < 8; r++) {
    ctws(R[r], I[r], g_twp[t * r]);
    SRr[r * 72 + t] = R[r]; SIr[r * 72 + t] = I[r];
  }
  __syncthreads();

  const int r = t >> 3, T = t & 7;
#pragma unroll
  for (int k = 0; k < 8; k++) {
    R[k] = SRr[r * 72 + T + (k << 3)];
    I[k] = SIr[r * 72 + T + (k << 3)];
  }
  fft8s(R, I, NEG1, CCp, NCp);
#pragma unroll
  for (int rp = 1; rp < 8; rp++) ctws(R[rp], I[rp], g_twp[8 * T * rp]);
  transpose8u(R, T);
  transpose8u(I, T);
  fft8s(R, I, NEG1, CCp, NCp);

  // modulus (packed): h = sqrt(raw2/512^2 + 1e-8*512^2) = 512*m_true
  const u64 SC2 = pk2(3.814697265625e-6f, 3.814697265625e-6f);
  const u64 EPS = pk2(2.62144e-3f, 2.62144e-3f);
  float a2loc = 0.f;
#pragma unroll
  for (int k3 = 0; k3 < 8; k3++) {
    u64 m2 = pfma(R[k3], R[k3], pmul(I[k3], I[k3]));
    m2 = pfma(m2, SC2, EPS);
    float2 mm = up2(m2);
    if (f == 0) a2loc += mm.x + mm.y;
    ((__half2*)g_m)[base + (k3 << 6) + t] = __floats2half2_rn(sqrtf(mm.x), sqrtf(mm.y));
  }
  if (f == 0) {
    int lane = tid & 31, wp = tid >> 5;
    a2loc += __shfl_down_sync(0xffffffffu, a2loc, 16);
    a2loc += __shfl_down_sync(0xffffffffu, a2loc, 8);
    a2loc += __shfl_down_sync(0xffffffffu, a2loc, 4);
    a2loc += __shfl_down_sync(0xffffffffu, a2loc, 2);
    a2loc += __shfl_down_sync(0xffffffffu, a2loc, 1);
    if (lane == 0) red[wp] = a2loc;
    __syncthreads();
    if (tid == 0) {
      float s = 0.f;
#pragma unroll
      for (int w2 = 0; w2 < 8; w2++) s += red[w2];
      atomicAdd(&g_a2, s);
    }
  }
}

// ---- stage 3: all grams via HMMA, double-buffered pipeline ----
#define SB 1040

__device__ __forceinline__ void mma16816(float c[4], unsigned a0, unsigned a1, unsigned a2,
                                         unsigned a3, unsigned b0, unsigned b1) {
  asm volatile("mma.sync.aligned.m16n8k16.row.col.f32.f16.f16.f32 "
               "{%0,%1,%2,%3}, {%4,%5,%6,%7}, {%8,%9}, {%0,%1,%2,%3};"
               : "+f"(c[0]), "+f"(c[1]), "+f"(c[2]), "+f"(c[3])
               : "r"(a0), "r"(a1), "r"(a2), "r"(a3), "r"(b0), "r"(b1));
}

__global__ void __launch_bounds__(256) gram_kernel() {
  __shared__ __align__(16) unsigned char sm[2][24 * SB];
  const int g = blockIdx.x;
  const int tid = threadIdx.x;
  const int w = tid >> 5, lane = tid & 31;
  const bool jg = (g < 16);
  const size_t chunkbase = (size_t)blockIdx.y * 8192;

  for (int i = tid; i < 7 * 65; i += 256) {
    ((uint4*)(sm[0] + 17 * SB))[i] = make_uint4(0, 0, 0, 0);
    ((uint4*)(sm[1] + 17 * SB))[i] = make_uint4(0, 0, 0, 0);
  }

  const int ccc = tid & 63, rbase = tid >> 6;
  const uint4* src[5];
#pragma unroll
  for (int p = 0; p < 4; p++) {
    int rr = rbase + 4 * p;
    int fidx = jg ? (1 + rr * 16 + g) : (1 + (g - 16) * 16 + rr);
    src[p] = (const uint4*)(g_m + (size_t)fidx * NPIX) + ccc;
  }
  src[4] = (const uint4*)g_m + tid;
  const bool do_lp = jg && (tid < 64);

  float c0[4] = {0,0,0,0}, c1[4] = {0,0,0,0}, c2[4] = {0,0,0,0};

  unsigned smb[2] = { (unsigned)__cvta_generic_to_shared(sm[0]),
                      (unsigned)__cvta_generic_to_shared(sm[1]) };
  const unsigned arel = ((lane & 7) + ((lane >> 3) & 1) * 8) * SB + (lane >> 4) * 16;
  const unsigned lrel = (16 + (lane & 7)) * SB + ((lane >> 3) & 1) * 16;
  const unsigned pwarp = w * 128;
  const unsigned dst0 = rbase * SB + ccc * 16;

  uint4 rg[5];
  {
    const size_t P4 = chunkbase >> 3;
#pragma unroll
    for (int p = 0; p < 4; p++) rg[p] = src[p][P4];
    if (do_lp) rg[4] = src[4][P4];
#pragma unroll
    for (int p = 0; p < 4; p++)
      *(uint4*)(sm[0] + dst0 + p * 4 * SB) = rg[p];
    if (do_lp) *(uint4*)(sm[0] + 16 * SB + tid * 16) = rg[4];
  }
  __syncthreads();

  for (int it = 0; it < 16; it++) {
    const int b = it & 1;
    if (it < 15) {
      const size_t P4 = (chunkbase + (it + 1) * 512) >> 3;
#pragma unroll
      for (int p = 0; p < 4; p++) rg[p] = src[p][P4];
      if (do_lp) rg[4] = src[4][P4];
    }

#pragma unroll
    for (int ks = 0; ks < 4; ks++) {
      unsigned pb = pwarp + ks * 32;
      unsigned a0, a1, a2, a3;
      asm volatile("ldmatrix.sync.aligned.m8n8.x4.shared.b16 {%0,%1,%2,%3}, [%4];"
                   : "=r"(a0), "=r"(a1), "=r"(a2), "=r"(a3) : "r"(smb[b] + arel + pb));
      mma16816(c0, a0, a1, a2, a3, a0, a2);
      mma16816(c1, a0, a1, a2, a3, a1, a3);
      if (jg) {
        unsigned l0, l1;
        asm volatile("ldmatrix.sync.aligned.m8n8.x2.shared.b16 {%0,%1}, [%2];"
                     : "=r"(l0), "=r"(l1) : "r"(smb[b] + lrel + pb));
        mma16816(c2, a0, a1, a2, a3, l0, l1);
      }
    }

    if (it < 15) {
      unsigned char* dbuf = sm[1 - b];
#pragma unroll
      for (int p = 0; p < 4; p++)
        *(uint4*)(dbuf + dst0 + p * 4 * SB) = rg[p];
      if (do_lp) *(uint4*)(dbuf + 16 * SB + tid * 16) = rg[4];
    }
    __syncthreads();
  }

  float* Gs = (float*)sm;
  const int row0 = lane >> 2, colb = 2 * (lane & 3);
  float* W = Gs + w * 384;
  W[row0 * 24 + colb]            = c0[0];
  W[row0 * 24 + colb + 1]        = c0[1];
  W[(row0 + 8) * 24 + colb]      = c0[2];
  W[(row0 + 8) * 24 + colb + 1]  = c0[3];
  W[row0 * 24 + 8 + colb]        = c1[0];
  W[row0 * 24 + 8 + colb + 1]    = c1[1];
  W[(row0 + 8) * 24 + 8 + colb]     = c1[2];
  W[(row0 + 8) * 24 + 8 + colb + 1] = c1[3];
  W[row0 * 24 + 16 + colb]       = c2[0];
  W[row0 * 24 + 16 + colb + 1]   = c2[1];
  W[(row0 + 8) * 24 + 16 + colb]     = c2[2];
  W[(row0 + 8) * 24 + 16 + colb + 1] = c2[3];
  __syncthreads();
  for (int e = tid; e < 384; e += 256) {
    float s = 0.f;
#pragma unroll
    for (int w2 = 0; w2 < 8; w2++) s += Gs[w2 * 384 + e];
    atomicAdd(&g_gram[g * 384 + e], s);
  }
}

// ---- stage 4: assemble (reference ordering); scale 1/(NPIX*512^2) ----
__global__ void assemble_kernel(float* __restrict__ out) {
  const int t = threadIdx.x;
  const float inv = 1.0f / ((float)NPIX * 262144.0f);
  if (t == 0) out[0] = g_a2 * inv;
  if (t >= 256) return;
  int i = t >> 4, j = t & 15;
  int rowsum = 152 * i + 16 * (15 * i - (i * (i - 1)) / 2);
  int segsum = 2 * j + ((i < 15) ? (15 - i) * j : 0) + 15 * j - (j * (j - 1)) / 2;
  int pos = 1 + rowsum + segsum;
  const float* GA = g_gram + (j * 16 + i) * 24;
  out[pos++] = GA[i] * inv;
  out[pos++] = GA[16] * inv;
  if (i < 15)
    for (int l = i + 1; l < 16; l++)
      out[pos++] = g_gram[(j * 16 + i) * 24 + l] * inv;
  if (j < 15)
    for (int l = j + 1; l < 16; l++)
      out[pos++] = g_gram[((16 + i) * 16 + j) * 24 + l] * inv;
}

extern "C" void kernel_launch(void* const* d_in, const int* in_sizes, int n_in,
                              void* d_out, int out_size) {
  const float2* xh2 = (const float2*)d_in[0];
  const float* pre  = (const float*)d_in[1];
  const float* pim  = (const float*)d_in[2];
  float* out = (float*)d_out;

  init_kernel<<<1, 256>>>();
  rows_kernel<<<dim3(NSIDE / 8, NF), 256>>>(xh2, pre, pim);
  cols_kernel<<<dim3(64, NF), 256>>>();     // 64 * 4 = 256 x-pair columns per filter
  gram_kernel<<<dim3(32, 32), 256>>>();
  assemble_kernel<<<1, 256>>>(out);
}

// round 9
// speedup vs baseline: 1.0976x; 1.0976x over previous
#include <cuda_runtime.h>
#include <cuda_fp16.h>
#include <math.h>

#define NSIDE 512
#define NPIX  (512*512)
#define NF    257

typedef __half2 h2;

// ---- scratch ----
__device__ __align__(16) h2     g_tmpR[NF * NPIX / 2];  // re plane, [f][q][y], fp16 x-pairs
__device__ __align__(16) h2     g_tmpI[NF * NPIX / 2];  // im plane
__device__ __align__(16) __half g_m[NF * NPIX];         // modulus*512, [f][q][y][parity]
__device__ float g_gram[32 * 16 * 24];
__device__ float g_a2;
__device__ uint2 g_twh[512];                            // fp16 twiddles {(c,c),(s,s)}

__device__ __forceinline__ unsigned h2u(h2 a){ return *reinterpret_cast<unsigned*>(&a); }
__device__ __forceinline__ h2 u2h(unsigned a){ return *reinterpret_cast<h2*>(&a); }

#define DECL_H_CONSTS \
  const h2 CC = __floats2half2_rn(0.70710678118654752440f, 0.70710678118654752440f); \
  const h2 NC = __floats2half2_rn(-0.70710678118654752440f, -0.70710678118654752440f);

// 8-pt DFT, +i sign, natural order, fp16 SoA (2 pixels per op, zero swaps)
__device__ __forceinline__ void fft8h(h2 R[8], h2 I[8], h2 CC, h2 NC) {
  h2 es0R=__hadd2(R[0],R[4]), es0I=__hadd2(I[0],I[4]);
  h2 ed0R=__hsub2(R[0],R[4]), ed0I=__hsub2(I[0],I[4]);
  h2 es1R=__hadd2(R[2],R[6]), es1I=__hadd2(I[2],I[6]);
  h2 ed1R=__hsub2(R[2],R[6]), ed1I=__hsub2(I[2],I[6]);
  h2 E0R=__hadd2(es0R,es1R), E0I=__hadd2(es0I,es1I);
  h2 E2R=__hsub2(es0R,es1R), E2I=__hsub2(es0I,es1I);
  h2 E1R=__hsub2(ed0R,ed1I), E1I=__hadd2(ed0I,ed1R);   // ed0 + i*ed1
  h2 E3R=__hadd2(ed0R,ed1I), E3I=__hsub2(ed0I,ed1R);   // ed0 - i*ed1
  h2 os0R=__hadd2(R[1],R[5]), os0I=__hadd2(I[1],I[5]);
  h2 od0R=__hsub2(R[1],R[5]), od0I=__hsub2(I[1],I[5]);
  h2 os1R=__hadd2(R[3],R[7]), os1I=__hadd2(I[3],I[7]);
  h2 od1R=__hsub2(R[3],R[7]), od1I=__hsub2(I[3],I[7]);
  h2 O0R=__hadd2(os0R,os1R), O0I=__hadd2(os0I,os1I);
  h2 O2R=__hsub2(os0R,os1R), O2I=__hsub2(os0I,os1I);
  h2 O1R=__hsub2(od0R,od1I), O1I=__hadd2(od0I,od1R);
  h2 O3R=__hadd2(od0R,od1I), O3I=__hsub2(od0I,od1R);
  h2 O1tR=__hmul2(__hsub2(O1R,O1I), CC);
  h2 O1tI=__hmul2(__hadd2(O1R,O1I), CC);
  h2 O3tR=__hmul2(__hadd2(O3R,O3I), NC);   // -C(x+y)
  h2 O3tI=__hmul2(__hsub2(O3R,O3I), CC);   // C(x-y)
  R[0]=__hadd2(E0R,O0R);  I[0]=__hadd2(E0I,O0I);
  R[4]=__hsub2(E0R,O0R);  I[4]=__hsub2(E0I,O0I);
  R[1]=__hadd2(E1R,O1tR); I[1]=__hadd2(E1I,O1tI);
  R[5]=__hsub2(E1R,O1tR); I[5]=__hsub2(E1I,O1tI);
  R[2]=__hsub2(E2R,O2I);  I[2]=__hadd2(E2I,O2R);       // E2 + i*O2
  R[6]=__hadd2(E2R,O2I);  I[6]=__hsub2(E2I,O2R);       // E2 - i*O2
  R[3]=__hadd2(E3R,O3tR); I[3]=__hadd2(E3I,O3tI);
  R[7]=__hsub2(E3R,O3tR); I[7]=__hsub2(E3I,O3tI);
}

__device__ __forceinline__ void ctwh(h2& R, h2& I, uint2 w) {   // *(c + i s)
  h2 wc = u2h(w.x), ws = u2h(w.y), nws = u2h(w.y ^ 0x80008000u);
  h2 r = __hfma2(I, nws, __hmul2(R, wc));
  h2 i = __hfma2(R, ws,  __hmul2(I, wc));
  R = r; I = i;
}

// 8x8 transpose among 8 lanes differing in low-3 lane bits (32-bit shuffles)
__device__ __forceinline__ void transpose8h(h2 v[8], int f3) {
#pragma unroll
  for (int mb = 0; mb < 3; mb++) {
    const int m = 1 << mb;
#pragma unroll
    for (int i = 0; i < 8; i++) {
      if ((i & m) == 0) {
        const int ip = i | m;
        const bool hi = (f3 & m) != 0;
        unsigned send = h2u(hi ? v[i] : v[ip]);
        unsigned got = __shfl_xor_sync(0xffffffffu, send, m);
        if (hi) v[i] = u2h(got); else v[ip] = u2h(got);
      }
    }
  }
}

__global__ void init_kernel() {
  int t = threadIdx.x;
  for (int m = t; m < 512; m += 256) {
    float s, c;
    sincospif((float)m * (1.0f / 256.0f), &s, &c);
    h2 wc = __floats2half2_rn(c, c), ws = __floats2half2_rn(s, s);
    g_twh[m] = make_uint2(h2u(wc), h2u(ws));
  }
  for (int i = t; i < 32 * 384; i += 256) g_gram[i] = 0.f;
  if (t == 0) g_a2 = 0.f;
}

// ---- stage 1: product + 512-pt IFFT along x (fp16 SoA, y-pairs); repack to x-pairs ----
__global__ void __launch_bounds__(256) rows_kernel(const float2* __restrict__ xh2,
                                                   const float* __restrict__ pre,
                                                   const float* __restrict__ pim) {
  __shared__ h2 SR[2304], SI[2304];   // 18 KB total; stage 4*576, final [p][512]
  DECL_H_CONSTS
  const int tid = threadIdx.x;
  const int p = tid >> 6, t = tid & 63;
  const int f = blockIdx.y;
  const int y0 = blockIdx.x << 3;
  const size_t rEo = (size_t)(y0 + 2 * p) * NSIDE, rOo = rEo + NSIDE;
  const size_t fb = (size_t)f * NPIX;

  h2 R[8], I[8];
#pragma unroll
  for (int q = 0; q < 8; q++) {
    int x = t + (q << 6);
    float2 xcE = xh2[rEo + x], xcO = xh2[rOo + x];
    float prE = __ldcs(pre + fb + rEo + x), piE = __ldcs(pim + fb + rEo + x);
    float prO = __ldcs(pre + fb + rOo + x), piO = __ldcs(pim + fb + rOo + x);
    R[q] = __floats2half2_rn(xcE.x * prE - xcE.y * piE, xcO.x * prO - xcO.y * piO);
    I[q] = __floats2half2_rn(xcE.x * piE + xcE.y * prE, xcO.x * piO + xcO.y * prO);
  }
  fft8h(R, I, CC, NC);
  h2 *SRr = SR + p * 576, *SIr = SI + p * 576;
  SRr[t] = R[0]; SIr[t] = I[0];
#pragma unroll
  for (int r = 1; r < 8; r++) {
    ctwh(R[r], I[r], g_twh[t * r]);
    SRr[r * 72 + t] = R[r]; SIr[r * 72 + t] = I[r];
  }
  __syncthreads();

  const int r = t >> 3, T = t & 7;
#pragma unroll
  for (int q = 0; q < 8; q++) {
    R[q] = SRr[r * 72 + T + (q << 3)];
    I[q] = SIr[r * 72 + T + (q << 3)];
  }
  fft8h(R, I, CC, NC);
#pragma unroll
  for (int rp = 1; rp < 8; rp++) ctwh(R[rp], I[rp], g_twh[8 * T * rp]);
  transpose8h(R, T);
  transpose8h(I, T);
  fft8h(R, I, CC, NC);
  __syncthreads();

  // final: [p][x] planes (h2 = y-pair), then repack to x-pairs per y
#pragma unroll
  for (int k3 = 0; k3 < 8; k3++) {
    int x = (k3 << 6) + t;
    SR[p * 512 + x] = R[k3];
    SI[p * 512 + x] = I[k3];
  }
  __syncthreads();

  {
    const int q = tid;   // x-pair index 0..255
    unsigned hR[8], hI[8];
#pragma unroll
    for (int pp = 0; pp < 4; pp++) {
      uint2 ra = *(const uint2*)&SR[pp * 512 + 2 * q];   // (x0: yE,yO), (x1: yE,yO)
      uint2 ia = *(const uint2*)&SI[pp * 512 + 2 * q];
      hR[2*pp]   = __byte_perm(ra.x, ra.y, 0x5410);      // yE: (re x0, re x1)
      hR[2*pp+1] = __byte_perm(ra.x, ra.y, 0x7632);      // yO
      hI[2*pp]   = __byte_perm(ia.x, ia.y, 0x5410);
      hI[2*pp+1] = __byte_perm(ia.x, ia.y, 0x7632);
    }
    size_t base = ((size_t)f * 256 + q) * 512 + y0;
    uint4* dR = reinterpret_cast<uint4*>(g_tmpR + base);
    dR[0] = make_uint4(hR[0], hR[1], hR[2], hR[3]);
    dR[1] = make_uint4(hR[4], hR[5], hR[6], hR[7]);
    uint4* dI = reinterpret_cast<uint4*>(g_tmpI + base);
    dI[0] = make_uint4(hI[0], hI[1], hI[2], hI[3]);
    dI[1] = make_uint4(hI[4], hI[5], hI[6], hI[7]);
  }
}

// ---- stage 2: 512-pt IFFT along y (fp16 SoA x-pairs, contiguous) + fp32 modulus ----
__global__ void __launch_bounds__(256) cols_kernel() {
  __shared__ h2 SR[2304], SI[2304];
  __shared__ float red[8];
  DECL_H_CONSTS
  const int tid = threadIdx.x;
  const int cc = tid >> 6, t = tid & 63;
  const int f = blockIdx.y;
  const int q = (blockIdx.x << 2) + cc;
  const size_t base = ((size_t)f * 256 + q) * 512;

  h2 R[8], I[8];
#pragma unroll
  for (int k = 0; k < 8; k++) {
    R[k] = g_tmpR[base + t + (k << 6)];
    I[k] = g_tmpI[base + t + (k << 6)];
  }
  fft8h(R, I, CC, NC);
  h2 *SRr = SR + cc * 576, *SIr = SI + cc * 576;
  SRr[t] = R[0]; SIr[t] = I[0];
#pragma unroll
  for (int r = 1; r < 8; r++) {
    ctwh(R[r], I[r], g_twh[t * r]);
    SRr[r * 72 + t] = R[r]; SIr[r * 72 + t] = I[r];
  }
  __syncthreads();

  const int r = t >> 3, T = t & 7;
#pragma unroll
  for (int k = 0; k < 8; k++) {
    R[k] = SRr[r * 72 + T + (k << 3)];
    I[k] = SIr[r * 72 + T + (k << 3)];
  }
  fft8h(R, I, CC, NC);
#pragma unroll
  for (int rp = 1; rp < 8; rp++) ctwh(R[rp], I[rp], g_twh[8 * T * rp]);
  transpose8h(R, T);
  transpose8h(I, T);
  fft8h(R, I, CC, NC);

  // modulus in fp32: stored h = 512*m_true = sqrt(raw^2/512^2 + 1e-8*512^2)
  const float SC2 = 3.814697265625e-6f, EPS = 2.62144e-3f;
  float a2loc = 0.f;
#pragma unroll
  for (int k3 = 0; k3 < 8; k3++) {
    float2 rr = __half22float2(R[k3]), ii = __half22float2(I[k3]);
    float m0 = sqrtf((rr.x * rr.x + ii.x * ii.x) * SC2 + EPS);
    float m1 = sqrtf((rr.y * rr.y + ii.y * ii.y) * SC2 + EPS);
    if (f == 0) a2loc += m0 * m0 + m1 * m1;
    ((h2*)g_m)[base + (k3 << 6) + t] = __floats2half2_rn(m0, m1);
  }
  if (f == 0) {
    int lane = tid & 31, wp = tid >> 5;
    a2loc += __shfl_down_sync(0xffffffffu, a2loc, 16);
    a2loc += __shfl_down_sync(0xffffffffu, a2loc, 8);
    a2loc += __shfl_down_sync(0xffffffffu, a2loc, 4);
    a2loc += __shfl_down_sync(0xffffffffu, a2loc, 2);
    a2loc += __shfl_down_sync(0xffffffffu, a2loc, 1);
    if (lane == 0) red[wp] = a2loc;
    __syncthreads();
    if (tid == 0) {
      float s = 0.f;
#pragma unroll
      for (int w2 = 0; w2 < 8; w2++) s += red[w2];
      atomicAdd(&g_a2, s);
    }
  }
}

// ---- stage 3: all grams via HMMA, double-buffered pipeline (unchanged from R5) ----
#define SB 1040

__device__ __forceinline__ void mma16816(float c[4], unsigned a0, unsigned a1, unsigned a2,
                                         unsigned a3, unsigned b0, unsigned b1) {
  asm volatile("mma.sync.aligned.m16n8k16.row.col.f32.f16.f16.f32 "
               "{%0,%1,%2,%3}, {%4,%5,%6,%7}, {%8,%9}, {%0,%1,%2,%3};"
               : "+f"(c[0]), "+f"(c[1]), "+f"(c[2]), "+f"(c[3])
               : "r"(a0), "r"(a1), "r"(a2), "r"(a3), "r"(b0), "r"(b1));
}

__global__ void __launch_bounds__(256) gram_kernel() {
  __shared__ __align__(16) unsigned char sm[2][24 * SB];
  const int g = blockIdx.x;
  const int tid = threadIdx.x;
  const int w = tid >> 5, lane = tid & 31;
  const bool jg = (g < 16);
  const size_t chunkbase = (size_t)blockIdx.y * 8192;

  for (int i = tid; i < 7 * 65; i += 256) {
    ((uint4*)(sm[0] + 17 * SB))[i] = make_uint4(0, 0, 0, 0);
    ((uint4*)(sm[1] + 17 * SB))[i] = make_uint4(0, 0, 0, 0);
  }

  const int ccc = tid & 63, rbase = tid >> 6;
  const uint4* src[5];
#pragma unroll
  for (int p = 0; p < 4; p++) {
    int rr = rbase + 4 * p;
    int fidx = jg ? (1 + rr * 16 + g) : (1 + (g - 16) * 16 + rr);
    src[p] = (const uint4*)(g_m + (size_t)fidx * NPIX) + ccc;
  }
  src[4] = (const uint4*)g_m + tid;
  const bool do_lp = jg && (tid < 64);

  float c0[4] = {0,0,0,0}, c1[4] = {0,0,0,0}, c2[4] = {0,0,0,0};

  unsigned smb[2] = { (unsigned)__cvta_generic_to_shared(sm[0]),
                      (unsigned)__cvta_generic_to_shared(sm[1]) };
  const unsigned arel = ((lane & 7) + ((lane >> 3) & 1) * 8) * SB + (lane >> 4) * 16;
  const unsigned lrel = (16 + (lane & 7)) * SB + ((lane >> 3) & 1) * 16;
  const unsigned pwarp = w * 128;
  const unsigned dst0 = rbase * SB + ccc * 16;

  uint4 rg[5];
  {
    const size_t P4 = chunkbase >> 3;
#pragma unroll
    for (int p = 0; p < 4; p++) rg[p] = src[p][P4];
    if (do_lp) rg[4] = src[4][P4];
#pragma unroll
    for (int p = 0; p < 4; p++)
      *(uint4*)(sm[0] + dst0 + p * 4 * SB) = rg[p];
    if (do_lp) *(uint4*)(sm[0] + 16 * SB + tid * 16) = rg[4];
  }
  __syncthreads();

  for (int it = 0; it < 16; it++) {
    const int b = it & 1;
    if (it < 15) {
      const size_t P4 = (chunkbase + (it + 1) * 512) >> 3;
#pragma unroll
      for (int p = 0; p < 4; p++) rg[p] = src[p][P4];
      if (do_lp) rg[4] = src[4][P4];
    }

#pragma unroll
    for (int ks = 0; ks < 4; ks++) {
      unsigned pb = pwarp + ks * 32;
      unsigned a0, a1, a2, a3;
      asm volatile("ldmatrix.sync.aligned.m8n8.x4.shared.b16 {%0,%1,%2,%3}, [%4];"
                   : "=r"(a0), "=r"(a1), "=r"(a2), "=r"(a3) : "r"(smb[b] + arel + pb));
      mma16816(c0, a0, a1, a2, a3, a0, a2);
      mma16816(c1, a0, a1, a2, a3, a1, a3);
      if (jg) {
        unsigned l0, l1;
        asm volatile("ldmatrix.sync.aligned.m8n8.x2.shared.b16 {%0,%1}, [%2];"
                     : "=r"(l0), "=r"(l1) : "r"(smb[b] + lrel + pb));
        mma16816(c2, a0, a1, a2, a3, l0, l1);
      }
    }

    if (it < 15) {
      unsigned char* dbuf = sm[1 - b];
#pragma unroll
      for (int p = 0; p < 4; p++)
        *(uint4*)(dbuf + dst0 + p * 4 * SB) = rg[p];
      if (do_lp) *(uint4*)(dbuf + 16 * SB + tid * 16) = rg[4];
    }
    __syncthreads();
  }

  float* Gs = (float*)sm;
  const int row0 = lane >> 2, colb = 2 * (lane & 3);
  float* W = Gs + w * 384;
  W[row0 * 24 + colb]            = c0[0];
  W[row0 * 24 + colb + 1]        = c0[1];
  W[(row0 + 8) * 24 + colb]      = c0[2];
  W[(row0 + 8) * 24 + colb + 1]  = c0[3];
  W[row0 * 24 + 8 + colb]        = c1[0];
  W[row0 * 24 + 8 + colb + 1]    = c1[1];
  W[(row0 + 8) * 24 + 8 + colb]     = c1[2];
  W[(row0 + 8) * 24 + 8 + colb + 1] = c1[3];
  W[row0 * 24 + 16 + colb]       = c2[0];
  W[row0 * 24 + 16 + colb + 1]   = c2[1];
  W[(row0 + 8) * 24 + 16 + colb]     = c2[2];
  W[(row0 + 8) * 24 + 16 + colb + 1] = c2[3];
  __syncthreads();
  for (int e = tid; e < 384; e += 256) {
    float s = 0.f;
#pragma unroll
    for (int w2 = 0; w2 < 8; w2++) s += Gs[w2 * 384 + e];
    atomicAdd(&g_gram[g * 384 + e], s);
  }
}

// ---- stage 4: assemble (reference ordering); scale 1/(NPIX*512^2) ----
__global__ void assemble_kernel(float* __restrict__ out) {
  const int t = threadIdx.x;
  const float inv = 1.0f / ((float)NPIX * 262144.0f);
  if (t == 0) out[0] = g_a2 * inv;
  if (t >= 256) return;
  int i = t >> 4, j = t & 15;
  int rowsum = 152 * i + 16 * (15 * i - (i * (i - 1)) / 2);
  int segsum = 2 * j + ((i < 15) ? (15 - i) * j : 0) + 15 * j - (j * (j - 1)) / 2;
  int pos = 1 + rowsum + segsum;
  const float* GA = g_gram + (j * 16 + i) * 24;
  out[pos++] = GA[i] * inv;
  out[pos++] = GA[16] * inv;
  if (i < 15)
    for (int l = i + 1; l < 16; l++)
      out[pos++] = g_gram[(j * 16 + i) * 24 + l] * inv;
  if (j < 15)
    for (int l = j + 1; l < 16; l++)
      out[pos++] = g_gram[((16 + i) * 16 + j) * 24 + l] * inv;
}

extern "C" void kernel_launch(void* const* d_in, const int* in_sizes, int n_in,
                              void* d_out, int out_size) {
  const float2* xh2 = (const float2*)d_in[0];
  const float* pre  = (const float*)d_in[1];
  const float* pim  = (const float*)d_in[2];
  float* out = (float*)d_out;

  init_kernel<<<1, 256>>>();
  rows_kernel<<<dim3(NSIDE / 8, NF), 256>>>(xh2, pre, pim);
  cols_kernel<<<dim3(64, NF), 256>>>();
  gram_kernel<<<dim3(32, 32), 256>>>();
  assemble_kernel<<<1, 256>>>(out);
}